// round 15
// baseline (speedup 1.0000x reference)
#include <cuda_runtime.h>
#include <cuda_fp16.h>
#include <cstdint>
#include <cstddef>

#define Bx 4
#define Vx 64
#define Ex 1024
#define Lx 1024
#define NR (Bx * Vx * Lx)          // 262144 rows

#define ASTR   264                 // gemm1 A row stride (halfs), full K resident
#define BCH    40                  // gemm1 B chunk row stride (halfs), padded
#define ZST    136                 // gemm1 epilogue stage row stride (halfs)
#define XZSTR  520                 // attn XZ row stride (halfs)
#define BSS    36                  // attn score row stride (floats)

__device__ __align__(16) __half g_Mc[16 * 128 * BCH]; // M chunked: [kt*2+nh][n 128][40]
__device__ __align__(16) float  g_r[256];             // r[n] = sum_c bq[c]*Wk[c][n]
__device__ __align__(16) float  g_Mp[4 * 256 * 256];  // precompute partials [dq][n][k]
__device__ __align__(16) float  g_rp[4 * 256];        // r partials [dq][n]
__device__ __align__(16) __half g_XZ[(size_t)NR * 512];   // row: [Xh(256) | Z+r (256)]
__device__ __align__(16) float  g_ewS[(size_t)Bx * Lx * Ex]; // ew, l-major staging

__device__ __forceinline__ unsigned packh2(float a, float b) {
    __half2 h = __floats2half2_rn(a, b);
    return *reinterpret_cast<unsigned*>(&h);
}

__device__ __forceinline__ void mma_f16(float (&d)[4], const unsigned (&a)[4],
                                        unsigned b0, unsigned b1) {
    asm volatile("mma.sync.aligned.m16n8k16.row.col.f32.f16.f16.f32 "
                 "{%0,%1,%2,%3}, {%4,%5,%6,%7}, {%8,%9}, {%0,%1,%2,%3};"
                 : "+f"(d[0]), "+f"(d[1]), "+f"(d[2]), "+f"(d[3])
                 : "r"(a[0]), "r"(a[1]), "r"(a[2]), "r"(a[3]), "r"(b0), "r"(b1));
}

__device__ __forceinline__ void ldsm_x4(unsigned &r0, unsigned &r1, unsigned &r2,
                                        unsigned &r3, const void* p) {
    unsigned a = (unsigned)__cvta_generic_to_shared(p);
    asm volatile("ldmatrix.sync.aligned.m8n8.x4.shared.b16 {%0,%1,%2,%3}, [%4];"
                 : "=r"(r0), "=r"(r1), "=r"(r2), "=r"(r3) : "r"(a));
}

__device__ __forceinline__ uint32_t smem_u32(const void* p) {
    return (uint32_t)__cvta_generic_to_shared(p);
}
__device__ __forceinline__ void mbar_init(uint32_t a, unsigned cnt) {
    asm volatile("mbarrier.init.shared.b64 [%0], %1;" :: "r"(a), "r"(cnt) : "memory");
}
__device__ __forceinline__ void mbar_expect_tx(uint32_t a, unsigned bytes) {
    asm volatile("mbarrier.arrive.expect_tx.shared.b64 _, [%0], %1;"
                 :: "r"(a), "r"(bytes) : "memory");
}
__device__ __forceinline__ void fence_proxy_async_sc() {
    asm volatile("fence.proxy.async.shared::cta;" ::: "memory");
}
__device__ __forceinline__ void bulk_g2s(uint32_t dst, const void* src,
                                         unsigned bytes, uint32_t mbar) {
    asm volatile("cp.async.bulk.shared::cta.global.mbarrier::complete_tx::bytes "
                 "[%0], [%1], %2, [%3];"
                 :: "r"(dst), "l"(src), "r"(bytes), "r"(mbar) : "memory");
}
__device__ __forceinline__ void mbar_wait(uint32_t a, unsigned parity) {
    asm volatile(
        "{\n\t.reg .pred P;\n\t"
        "WAITL_%=:\n\t"
        "mbarrier.try_wait.parity.acquire.cta.shared::cta.b64 P, [%0], %1, 0x989680;\n\t"
        "@P bra.uni WAITD_%=;\n\t"
        "bra.uni WAITL_%=;\n\t"
        "WAITD_%=:\n\t}"
        :: "r"(a), "r"(parity) : "memory");
}

// ---------------- K0a: partial M over d-quarters ----------------
__global__ void pre_a(const float* __restrict__ Wq, const float* __restrict__ bq,
                      const float* __restrict__ Wk)
{
    __shared__ float sWk[64];
    __shared__ float red[2];
    const int n = blockIdx.x, dq = blockIdx.y, j = threadIdx.x;
    if (j < 64) sWk[j] = Wk[(dq * 64 + j) * 256 + n];
    __syncthreads();
    float acc = 0.f;
    const float* wq = Wq + (dq * 64) * 256 + j;
    #pragma unroll 8
    for (int dd = 0; dd < 64; dd++)
        acc = fmaf(wq[dd * 256], sWk[dd], acc);
    g_Mp[(dq * 256 + n) * 256 + j] = acc;

    if (j < 64) {
        float pr = bq[dq * 64 + j] * sWk[j];
        #pragma unroll
        for (int off = 16; off > 0; off >>= 1)
            pr += __shfl_xor_sync(~0u, pr, off);
        if ((j & 31) == 0) red[j >> 5] = pr;
    }
    __syncthreads();
    if (j == 0) g_rp[dq * 256 + n] = red[0] + red[1];
}

// ---------------- K0b: sum partials -> fp16 M (chunked layout), r ----------------
__global__ void pre_b()
{
    const int n = blockIdx.x, j = threadIdx.x;   // n = M-col, j = k
    float s = g_Mp[n * 256 + j] + g_Mp[(256 + n) * 256 + j]
            + g_Mp[(512 + n) * 256 + j] + g_Mp[(768 + n) * 256 + j];
    const int kt = j >> 5, nh = n >> 7, nl = n & 127;
    g_Mc[((kt * 2 + nh) * 128 + nl) * BCH + (j & 31)] = __float2half_rn(s);
    if (j == 0)
        g_r[n] = g_rp[n] + g_rp[256 + n] + g_rp[512 + n] + g_rp[768 + n];
}

// ---------------- K1: single-pass convert + GEMM  Z = Xh @ M^T + r ----------------
// grid 2048: 128-row tile, ALL 256 n cols (hs read ONCE).
// A resident in smem; B streamed per (nh, kt) as one 10KB bulk, double-buffered.
// K loop: kt = 0..7 (8 chunks of 32 halfs per n-half).
__global__ __launch_bounds__(256, 2) void gemm1_kernel(const float* __restrict__ hs)
{
    extern __shared__ char smraw1[];
    __half* As = (__half*)smraw1;                        // 128 x ASTR      (67584 B)
    __half* Bb = As + 128 * ASTR;                        // 2 x 128 x BCH   (20480 B)
    float*  Sr = (float*)(Bb + 2 * 128 * BCH);           // 256 floats
    unsigned long long* mbF = (unsigned long long*)(Sr + 256);  // 2 mbarriers
    __half* Zst = Bb;                                    // epilogue overlay (17408 B)

    const int t = threadIdx.x, w = t >> 5, j = t & 31;
    const int r0 = blockIdx.x * 128;
    const int rA = j >> 2, cA = j & 3;
    const int mb_ = (w & 3) * 32, nb = (w >> 2) * 64;
    const uint32_t mb0 = smem_u32(mbF), mb1 = smem_u32(mbF + 1);

    if (t == 0) {
        mbar_init(mb0, 1);
        mbar_init(mb1, 1);
        fence_proxy_async_sc();
    }
    if (t < 64) ((float4*)Sr)[t] = __ldg(((const float4*)g_r) + t);
    __syncthreads();

    // issue B chunks 0,1 of n-half 0
    if (t == 0) {
        mbar_expect_tx(mb0, 128 * BCH * 2);
        bulk_g2s(smem_u32(Bb), g_Mc + (0 * 2 + 0) * 128 * BCH, 128 * BCH * 2, mb0);
        mbar_expect_tx(mb1, 128 * BCH * 2);
        bulk_g2s(smem_u32(Bb + 128 * BCH), g_Mc + (1 * 2 + 0) * 128 * BCH,
                 128 * BCH * 2, mb1);
    }

    // ---- stage A: LDG fp32 -> cvt -> STS (As) + STG (g_XZ X part) ----
    {
        const int tq = t & 3;           // 8-float segment within 32-float chunk
        const int rbase = t >> 2;       // 0..63
        #pragma unroll
        for (int s = 0; s < 16; s++) {
            const int row = rbase + (s & 1) * 64;
            const int c   = s >> 1;
            const float* hp = hs + (size_t)(r0 + row) * 256 + c * 32 + tq * 8;
            float4 f0 = *(const float4*)(hp);
            float4 f1 = *(const float4*)(hp + 4);
            uint4 o;
            o.x = packh2(f0.x, f0.y); o.y = packh2(f0.z, f0.w);
            o.z = packh2(f1.x, f1.y); o.w = packh2(f1.z, f1.w);
            *(uint4*)(As + row * ASTR + c * 32 + tq * 8) = o;
            *(uint4*)(g_XZ + (size_t)(r0 + row) * 512 + c * 32 + tq * 8) = o;
        }
    }
    __syncthreads();

    int ph0 = 0, ph1 = 0;

    #pragma unroll 1
    for (int nh = 0; nh < 2; nh++) {
        float acc[2][8][4];
        #pragma unroll
        for (int a = 0; a < 2; a++)
            #pragma unroll
            for (int c = 0; c < 8; c++)
                #pragma unroll
                for (int q = 0; q < 4; q++) acc[a][c][q] = 0.f;

        #pragma unroll 1
        for (int kt = 0; kt < 8; kt++) {
            const int b = kt & 1;
            if (b == 0) { mbar_wait(mb0, ph0); ph0 ^= 1; }
            else        { mbar_wait(mb1, ph1); ph1 ^= 1; }
            const __half* Bc = Bb + b * 128 * BCH;

            #pragma unroll
            for (int ks = 0; ks < 2; ks++) {
                unsigned a[2][4];
                #pragma unroll
                for (int mt = 0; mt < 2; mt++) {
                    int arow = mb_ + mt * 16 + (j & 7) + ((j >> 3) & 1) * 8;
                    ldsm_x4(a[mt][0], a[mt][1], a[mt][2], a[mt][3],
                            As + arow * ASTR + kt * 32 + ks * 16 + (j >> 4) * 8);
                }
                #pragma unroll
                for (int p = 0; p < 4; p++) {
                    unsigned b0, b1, b2, b3;
                    int brow = nb + p * 16 + (j >> 4) * 8 + (j & 7);
                    ldsm_x4(b0, b1, b2, b3,
                            Bc + brow * BCH + ks * 16 + ((j >> 3) & 1) * 8);
                    mma_f16(acc[0][2 * p],     a[0], b0, b1);
                    mma_f16(acc[1][2 * p],     a[1], b0, b1);
                    mma_f16(acc[0][2 * p + 1], a[0], b2, b3);
                    mma_f16(acc[1][2 * p + 1], a[1], b2, b3);
                }
            }
            __syncthreads();          // all warps done reading Bc
            if (t == 0 && kt < 6) {
                const int nkt = kt + 2;
                const __half* src = g_Mc + (nkt * 2 + nh) * 128 * BCH;
                if (b == 0) { mbar_expect_tx(mb0, 128 * BCH * 2);
                              bulk_g2s(smem_u32(Bb), src, 128 * BCH * 2, mb0); }
                else        { mbar_expect_tx(mb1, 128 * BCH * 2);
                              bulk_g2s(smem_u32(Bb + 128 * BCH), src, 128 * BCH * 2, mb1); }
            }
        }

        // ---- epilogue nh: fragments -> Zst (overlay on Bb) -> coalesced STG ----
        #pragma unroll
        for (int pp = 0; pp < 2; pp++) {
            if (((w & 3) >> 1) == pp) {
                #pragma unroll
                for (int mt = 0; mt < 2; mt++)
                    #pragma unroll
                    for (int nt = 0; nt < 8; nt++) {
                        int lrow = (mb_ & 63) + mt * 16 + rA;
                        int col  = nb + nt * 8 + 2 * cA;
                        float rc0 = Sr[nh * 128 + col], rc1 = Sr[nh * 128 + col + 1];
                        *(unsigned*)(Zst + lrow * ZST + col) =
                            packh2(acc[mt][nt][0] + rc0, acc[mt][nt][1] + rc1);
                        *(unsigned*)(Zst + (lrow + 8) * ZST + col) =
                            packh2(acc[mt][nt][2] + rc0, acc[mt][nt][3] + rc1);
                    }
            }
            __syncthreads();
            #pragma unroll
            for (int i = 0; i < 4; i++) {
                int idx = i * 256 + t, row = idx >> 4, q = idx & 15;
                *(uint4*)(g_XZ + (size_t)(r0 + pp * 64 + row) * 512
                          + 256 + nh * 128 + q * 8) =
                    *(const uint4*)(Zst + row * ZST + q * 8);
            }
            __syncthreads();
        }

        // issue first two chunks of n-half 1 (Bb free again)
        if (nh == 0 && t == 0) {
            mbar_expect_tx(mb0, 128 * BCH * 2);
            bulk_g2s(smem_u32(Bb), g_Mc + (0 * 2 + 1) * 128 * BCH, 128 * BCH * 2, mb0);
            mbar_expect_tx(mb1, 128 * BCH * 2);
            bulk_g2s(smem_u32(Bb + 128 * BCH), g_Mc + (1 * 2 + 1) * 128 * BCH,
                     128 * BCH * 2, mb1);
        }
    }
}

// ---------------- K2: per (b,l): banded S = (Z+r).X^T, softmax ----------------
__global__ __launch_bounds__(256, 2)
void attn_kernel(const int*   __restrict__ edge_index,
                 const float* __restrict__ edge_weight,
                 const float* __restrict__ attn_skip_p,
                 float* __restrict__ out)
{
    extern __shared__ char smraw[];
    __half* XZ = (__half*)smraw;                       // 64 x XZSTR (X | Z)
    float*  Ss = (float*)(XZ + 64 * XZSTR);            // 2 x 64 x BSS
    int*    Sd = (int*)(Ss + 2 * 64 * BSS);            // 1024
    float*  Sew = (float*)(Sd + 1024);                 // 1024
    unsigned long long* mb = (unsigned long long*)(Sew + 1024);

    const int bx = blockIdx.x;
    const int b = bx >> 10, l = bx & 1023;
    const int t = threadIdx.x, w = t >> 5, j = t & 31;
    const int rA = j >> 2, cA = j & 3;
    const uint32_t mba = smem_u32(mb);

    if (t == 0) {
        mbar_init(mba, 1);
        fence_proxy_async_sc();
        mbar_expect_tx(mba, 64 * 1024);
    }
    __syncthreads();
    if (t < 64) {
        size_t rowoff = ((size_t)(b * Vx + t) * Lx + l) * 512;
        bulk_g2s(smem_u32(XZ + t * XZSTR), g_XZ + rowoff, 1024, mba);
    }

    {
        const int base = bx * 2048;
        #pragma unroll
        for (int r = 0; r < 8; r++) {
            int idx = base + r * 256 + t;
            out[idx] = (float)edge_index[idx >> 10];
        }
    }
    {
        const int*   dsts = edge_index + Bx * Ex + b * Ex;
        const float* ews  = edge_weight + b * Ex;
        #pragma unroll
        for (int i = 0; i < 4; i++) {
            Sd[i * 256 + t]  = dsts[i * 256 + t];
            Sew[i * 256 + t] = ews[i * 256 + t];
        }
    }
    mbar_wait(mba, 0);
    __syncthreads();

    {
        float sacc[4][4];
        #pragma unroll
        for (int c = 0; c < 4; c++)
            #pragma unroll
            for (int q = 0; q < 4; q++) sacc[c][q] = 0.f;

        const int m0 = (w & 3) * 16;
        const int kh = w >> 2;

        #pragma unroll
        for (int ks = 0; ks < 8; ks++) {
            const int kc = kh * 128 + ks * 16;
            unsigned a[4];
            {
                int arow = m0 + (j & 7) + ((j >> 3) & 1) * 8;
                ldsm_x4(a[0], a[1], a[2], a[3],
                        XZ + arow * XZSTR + 256 + kc + (j >> 4) * 8);   // Z part
            }
            #pragma unroll
            for (int p = 0; p < 2; p++) {
                unsigned b0, b1, b2, b3;
                int nrow = (m0 + 1 + (2 * p + (j >> 4)) * 8 + (j & 7)) & 63;
                ldsm_x4(b0, b1, b2, b3,
                        XZ + nrow * XZSTR + kc + ((j >> 3) & 1) * 8);   // X part
                mma_f16(sacc[2 * p],     a, b0, b1);
                mma_f16(sacc[2 * p + 1], a, b2, b3);
            }
        }

        float* SsH = Ss + kh * 64 * BSS;
        #pragma unroll
        for (int nt = 0; nt < 4; nt++) {
            int row = m0 + rA;
            int col = nt * 8 + 2 * cA;
            *(float2*)(SsH + row * BSS + col)       = make_float2(sacc[nt][0], sacc[nt][1]);
            *(float2*)(SsH + (row + 8) * BSS + col) = make_float2(sacc[nt][2], sacc[nt][3]);
        }
    }
    __syncthreads();

    const float skip = attn_skip_p[0];
    const int g  = j >> 4;
    const int jj = j & 15;

    #pragma unroll
    for (int it = 0; it < 4; it++) {
        const int v  = it * 16 + w * 2 + g;
        const int dst = Sd[v * 16 + jj];
        const int col = (dst - (v & ~15) - 1) & 63;        // in [0,32)
        float sc = (Ss[v * BSS + col] + Ss[64 * BSS + v * BSS + col]) * 0.0625f;
        float m = sc;
        #pragma unroll
        for (int off = 8; off > 0; off >>= 1) m = fmaxf(m, __shfl_xor_sync(~0u, m, off));
        float e = __expf(sc - m);
        float Zt = e;
        #pragma unroll
        for (int off = 8; off > 0; off >>= 1) Zt += __shfl_xor_sync(~0u, Zt, off);
        const int eIdx = v * 16 + jj;
        g_ewS[(size_t)bx * 1024 + eIdx] =
            skip * Sew[eIdx] + (1.0f - skip) * e / Zt;
    }
}

// ---------------- K3: transpose ewS (l-major) -> out (e-major) ----------------
__global__ __launch_bounds__(256) void ewT_kernel(float* __restrict__ out)
{
    __shared__ float tile[32][33];
    const int b = blockIdx.z;
    const int l0 = blockIdx.x * 32, e0 = blockIdx.y * 32;
    const int x = threadIdx.x, y = threadIdx.y;
    #pragma unroll
    for (int i = y; i < 32; i += 8)
        tile[i][x] = g_ewS[((size_t)(b * 1024 + l0 + i)) * 1024 + e0 + x];
    __syncthreads();
    float* outEw = out + (size_t)2 * Bx * Ex * Lx;
    #pragma unroll
    for (int i = y; i < 32; i += 8)
        outEw[((size_t)(b * 1024 + e0 + i)) * 1024 + l0 + x] = tile[x][i];
}

extern "C" void kernel_launch(void* const* d_in, const int* in_sizes, int n_in,
                              void* d_out, int out_size)
{
    const float* hs = (const float*)d_in[0];
    const int*   ei = (const int*)  d_in[1];
    const float* ew = (const float*)d_in[2];
    const float* Wq = (const float*)d_in[3];
    const float* bq = (const float*)d_in[4];
    const float* Wk = (const float*)d_in[5];
    const float* bk = (const float*)d_in[6];
    const float* sk = (const float*)d_in[7];
    float* out = (float*)d_out;
    (void)bk;

    pre_a<<<dim3(256, 4), 256>>>(Wq, bq, Wk);
    pre_b<<<256, 256>>>();

    const int smem1 = 128 * ASTR * 2 + 2 * 128 * BCH * 2 + 256 * 4 + 16;
    cudaFuncSetAttribute(gemm1_kernel, cudaFuncAttributeMaxDynamicSharedMemorySize, smem1);
    gemm1_kernel<<<2048, 256, smem1>>>(hs);

    const int smem2 = 64 * XZSTR * 2 + 2 * 64 * BSS * 4 + 1024 * 4 * 2 + 16;
    cudaFuncSetAttribute(attn_kernel, cudaFuncAttributeMaxDynamicSharedMemorySize, smem2);
    attn_kernel<<<Bx * Lx, 256, smem2>>>(ei, ew, sk, out);

    ewT_kernel<<<dim3(32, 32, Bx), dim3(32, 8)>>>(out);
}

// round 16
// speedup vs baseline: 1.5278x; 1.5278x over previous
#include <cuda_runtime.h>
#include <cuda_fp16.h>
#include <cstdint>
#include <cstddef>

#define Bx 4
#define Vx 64
#define Ex 1024
#define Lx 1024
#define NR (Bx * Vx * Lx)          // 262144 rows

#define ASTR   264                 // As (X fp16) row stride, halfs
#define ZSTR   280                 // Zs row stride, halfs (280 -> conflict-free STS + LDSM)
#define BCH    40                  // B chunk row stride (halfs), padded
#define BSS    36                  // score row stride (floats)
#define CHB    (128 * BCH * 2)     // bytes per B chunk (10240)

__device__ __align__(16) __half g_Mc[16 * 128 * BCH]; // M chunked: [kt*2+nh][n 128][40]
__device__ __align__(16) float  g_r[256];             // r[n] = sum_c bq[c]*Wk[c][n]
__device__ __align__(16) float  g_Mp[4 * 256 * 256];  // precompute partials
__device__ __align__(16) float  g_rp[4 * 256];
__device__ __align__(16) float  g_ewS[(size_t)Bx * Lx * Ex]; // ew, l-major staging

__device__ __forceinline__ unsigned packh2(float a, float b) {
    __half2 h = __floats2half2_rn(a, b);
    return *reinterpret_cast<unsigned*>(&h);
}

__device__ __forceinline__ void mma_f16(float (&d)[4], const unsigned (&a)[4],
                                        unsigned b0, unsigned b1) {
    asm volatile("mma.sync.aligned.m16n8k16.row.col.f32.f16.f16.f32 "
                 "{%0,%1,%2,%3}, {%4,%5,%6,%7}, {%8,%9}, {%0,%1,%2,%3};"
                 : "+f"(d[0]), "+f"(d[1]), "+f"(d[2]), "+f"(d[3])
                 : "r"(a[0]), "r"(a[1]), "r"(a[2]), "r"(a[3]), "r"(b0), "r"(b1));
}

__device__ __forceinline__ void ldsm_x4(unsigned &r0, unsigned &r1, unsigned &r2,
                                        unsigned &r3, const void* p) {
    unsigned a = (unsigned)__cvta_generic_to_shared(p);
    asm volatile("ldmatrix.sync.aligned.m8n8.x4.shared.b16 {%0,%1,%2,%3}, [%4];"
                 : "=r"(r0), "=r"(r1), "=r"(r2), "=r"(r3) : "r"(a));
}

__device__ __forceinline__ uint32_t smem_u32(const void* p) {
    return (uint32_t)__cvta_generic_to_shared(p);
}
__device__ __forceinline__ void mbar_init(uint32_t a, unsigned cnt) {
    asm volatile("mbarrier.init.shared.b64 [%0], %1;" :: "r"(a), "r"(cnt) : "memory");
}
__device__ __forceinline__ void mbar_expect_tx(uint32_t a, unsigned bytes) {
    asm volatile("mbarrier.arrive.expect_tx.shared.b64 _, [%0], %1;"
                 :: "r"(a), "r"(bytes) : "memory");
}
__device__ __forceinline__ void fence_proxy_async_sc() {
    asm volatile("fence.proxy.async.shared::cta;" ::: "memory");
}
__device__ __forceinline__ void bulk_g2s(uint32_t dst, const void* src,
                                         unsigned bytes, uint32_t mbar) {
    asm volatile("cp.async.bulk.shared::cta.global.mbarrier::complete_tx::bytes "
                 "[%0], [%1], %2, [%3];"
                 :: "r"(dst), "l"(src), "r"(bytes), "r"(mbar) : "memory");
}
__device__ __forceinline__ void mbar_wait(uint32_t a, unsigned parity) {
    asm volatile(
        "{\n\t.reg .pred P;\n\t"
        "WAITL_%=:\n\t"
        "mbarrier.try_wait.parity.acquire.cta.shared::cta.b64 P, [%0], %1, 0x989680;\n\t"
        "@P bra.uni WAITD_%=;\n\t"
        "bra.uni WAITL_%=;\n\t"
        "WAITD_%=:\n\t}"
        :: "r"(a), "r"(parity) : "memory");
}

// ---------------- K0a: partial M over d-quarters ----------------
__global__ void pre_a(const float* __restrict__ Wq, const float* __restrict__ bq,
                      const float* __restrict__ Wk)
{
    __shared__ float sWk[64];
    __shared__ float red[2];
    const int n = blockIdx.x, dq = blockIdx.y, j = threadIdx.x;
    if (j < 64) sWk[j] = Wk[(dq * 64 + j) * 256 + n];
    __syncthreads();
    float acc = 0.f;
    const float* wq = Wq + (dq * 64) * 256 + j;
    #pragma unroll 8
    for (int dd = 0; dd < 64; dd++)
        acc = fmaf(wq[dd * 256], sWk[dd], acc);
    g_Mp[(dq * 256 + n) * 256 + j] = acc;

    if (j < 64) {
        float pr = bq[dq * 64 + j] * sWk[j];
        #pragma unroll
        for (int off = 16; off > 0; off >>= 1)
            pr += __shfl_xor_sync(~0u, pr, off);
        if ((j & 31) == 0) red[j >> 5] = pr;
    }
    __syncthreads();
    if (j == 0) g_rp[dq * 256 + n] = red[0] + red[1];
}

// ---------------- K0b: sum partials -> fp16 M (chunked layout), r ----------------
__global__ void pre_b()
{
    const int n = blockIdx.x, j = threadIdx.x;   // n = M-col, j = k
    float s = g_Mp[n * 256 + j] + g_Mp[(256 + n) * 256 + j]
            + g_Mp[(512 + n) * 256 + j] + g_Mp[(768 + n) * 256 + j];
    const int kt = j >> 5, nh = n >> 7, nl = n & 127;
    g_Mc[((kt * 2 + nh) * 128 + nl) * BCH + (j & 31)] = __float2half_rn(s);
    if (j == 0)
        g_r[n] = g_rp[n] + g_rp[256 + n] + g_rp[512 + n] + g_rp[768 + n];
}

// ---------------- K_ei: coalesced broadcast fill of the ei output ----------------
__global__ __launch_bounds__(256) void ei_kernel(const int* __restrict__ edge_index,
                                                 float* __restrict__ out)
{
    const int idx0 = (blockIdx.x * 256 + threadIdx.x) * 4;   // 4-aligned, same e for all 4
    const float v = (float)edge_index[idx0 >> 10];
    *(float4*)(out + idx0) = make_float4(v, v, v, v);
}

// ---------------- K1: FUSED  X-stage + Z=X@M^T+r + banded S + softmax ----------------
// grid 2048: CTA = (b, l0..l0+1). Rows r = li*64 + v (128 rows).
__global__ __launch_bounds__(256, 1)
void fused_kernel(const float* __restrict__ hs,
                  const int*   __restrict__ edge_index,
                  const float* __restrict__ edge_weight,
                  const float* __restrict__ attn_skip_p)
{
    extern __shared__ char smraw[];
    __half* As = (__half*)smraw;                 // 128 x ASTR   (67584 B)
    __half* Zs = As + 128 * ASTR;                // 128 x ZSTR   (71680 B)
    __half* Bb = Zs + 128 * ZSTR;                // 4 x 128 x BCH (40960 B)
    float*  Sr = (float*)(Bb + 4 * 128 * BCH);   // 256
    int*    Sd = (int*)(Sr + 256);               // 1024
    float*  Sew = (float*)(Sd + 1024);           // 1024
    unsigned long long* mbF = (unsigned long long*)(Sew + 1024);  // 4 mbarriers
    float*  Ss = (float*)Bb;                     // overlay after GEMM (18432 B <= Bb)

    const int bx = blockIdx.x;
    const int b = bx >> 9, l0 = (bx & 511) * 2;
    const int t = threadIdx.x, w = t >> 5, j = t & 31;
    const int rA = j >> 2, cA = j & 3;
    const int mb_ = (w & 3) * 32, nb = (w >> 2) * 64;

    uint32_t mba[4];
    #pragma unroll
    for (int i = 0; i < 4; i++) mba[i] = smem_u32(mbF + i);

    if (t == 0) {
        #pragma unroll
        for (int i = 0; i < 4; i++) mbar_init(mba[i], 1);
        fence_proxy_async_sc();
    }
    __syncthreads();

    // prologue: issue B chunks 0..3 (c = nh*8+kt; c<4 -> nh=0, kt=c)
    if (t == 0) {
        #pragma unroll
        for (int c = 0; c < 4; c++) {
            mbar_expect_tx(mba[c], CHB);
            bulk_g2s(smem_u32(Bb + c * 128 * BCH), g_Mc + (c * 2 + 0) * 128 * BCH,
                     CHB, mba[c]);
        }
    }

    // ---- stage X: LDG fp32 -> cvt -> STS (warp reads one contiguous 1KB row / iter) ----
    {
        #pragma unroll
        for (int i = 0; i < 16; i++) {
            int idx = i * 256 + t;
            int row = idx >> 5;           // 0..127 : r = li*64 + v
            int q   = idx & 31;           // 8-float segment
            int v = row & 63, li = row >> 6;
            const float* hp = hs + ((size_t)(b * Vx + v) * Lx + (l0 + li)) * 256 + q * 8;
            float4 f0 = *(const float4*)(hp);
            float4 f1 = *(const float4*)(hp + 4);
            uint4 o;
            o.x = packh2(f0.x, f0.y); o.y = packh2(f0.z, f0.w);
            o.z = packh2(f1.x, f1.y); o.w = packh2(f1.z, f1.w);
            *(uint4*)(As + row * ASTR + q * 8) = o;
        }
    }
    // stage r, dst, ew
    if (t < 64) ((float4*)Sr)[t] = __ldg(((const float4*)g_r) + t);
    {
        const int*   dsts = edge_index + Bx * Ex + b * Ex;
        const float* ews  = edge_weight + b * Ex;
        #pragma unroll
        for (int i = 0; i < 4; i++) {
            Sd[i * 256 + t]  = dsts[i * 256 + t];
            Sew[i * 256 + t] = ews[i * 256 + t];
        }
    }
    __syncthreads();

    // ---- GEMM: Z[128][256] = X @ M^T + r (two n-halves, 4-deep B ring) ----
    #pragma unroll 1
    for (int nh = 0; nh < 2; nh++) {
        float acc[2][8][4];
        #pragma unroll
        for (int a = 0; a < 2; a++)
            #pragma unroll
            for (int c = 0; c < 8; c++)
                #pragma unroll
                for (int q = 0; q < 4; q++) acc[a][c][q] = 0.f;

        #pragma unroll 1
        for (int kt = 0; kt < 8; kt++) {
            const int c = nh * 8 + kt;
            mbar_wait(mba[c & 3], (c >> 2) & 1);
            const __half* Bc = Bb + (c & 3) * 128 * BCH;

            #pragma unroll
            for (int ks = 0; ks < 2; ks++) {
                unsigned a[2][4];
                #pragma unroll
                for (int mt = 0; mt < 2; mt++) {
                    int arow = mb_ + mt * 16 + (j & 7) + ((j >> 3) & 1) * 8;
                    ldsm_x4(a[mt][0], a[mt][1], a[mt][2], a[mt][3],
                            As + arow * ASTR + kt * 32 + ks * 16 + (j >> 4) * 8);
                }
                #pragma unroll
                for (int p = 0; p < 4; p++) {
                    unsigned b0, b1, b2, b3;
                    int brow = nb + p * 16 + (j >> 4) * 8 + (j & 7);
                    ldsm_x4(b0, b1, b2, b3,
                            Bc + brow * BCH + ks * 16 + ((j >> 3) & 1) * 8);
                    mma_f16(acc[0][2 * p],     a[0], b0, b1);
                    mma_f16(acc[1][2 * p],     a[1], b0, b1);
                    mma_f16(acc[0][2 * p + 1], a[0], b2, b3);
                    mma_f16(acc[1][2 * p + 1], a[1], b2, b3);
                }
            }
            __syncthreads();              // all warps done with buffer (c&3)
            if (t == 0 && c + 4 < 16) {
                const int nc = c + 4;
                const int nh2 = nc >> 3, kt2 = nc & 7;
                mbar_expect_tx(mba[nc & 3], CHB);
                bulk_g2s(smem_u32(Bb + (nc & 3) * 128 * BCH),
                         g_Mc + (kt2 * 2 + nh2) * 128 * BCH, CHB, mba[nc & 3]);
            }
        }

        // epilogue: fragments + r -> Zs (conflict-free via ZSTR=280)
        #pragma unroll
        for (int mt = 0; mt < 2; mt++)
            #pragma unroll
            for (int nt = 0; nt < 8; nt++) {
                int lrow = mb_ + mt * 16 + rA;
                int col  = nb + nt * 8 + 2 * cA;
                float rc0 = Sr[nh * 128 + col], rc1 = Sr[nh * 128 + col + 1];
                *(unsigned*)(Zs + lrow * ZSTR + nh * 128 + col) =
                    packh2(acc[mt][nt][0] + rc0, acc[mt][nt][1] + rc1);
                *(unsigned*)(Zs + (lrow + 8) * ZSTR + nh * 128 + col) =
                    packh2(acc[mt][nt][2] + rc0, acc[mt][nt][3] + rc1);
            }
    }
    __syncthreads();   // Zs complete; all 16 B chunks consumed -> Ss overlay safe

    // ---- per-li: banded S = Z @ X[band]^T, softmax, ew store ----
    const float skip = attn_skip_p[0];
    const int g  = j >> 4;
    const int jj = j & 15;

    #pragma unroll 1
    for (int li = 0; li < 2; li++) {
        const int base = li * 64;
        {
            float sacc[4][4];
            #pragma unroll
            for (int c = 0; c < 4; c++)
                #pragma unroll
                for (int q = 0; q < 4; q++) sacc[c][q] = 0.f;

            const int m0 = (w & 3) * 16;
            const int kh = w >> 2;

            #pragma unroll
            for (int ks = 0; ks < 8; ks++) {
                const int kc = kh * 128 + ks * 16;
                unsigned a[4];
                {
                    int arow = base + m0 + (j & 7) + ((j >> 3) & 1) * 8;
                    ldsm_x4(a[0], a[1], a[2], a[3],
                            Zs + arow * ZSTR + kc + (j >> 4) * 8);
                }
                #pragma unroll
                for (int p = 0; p < 2; p++) {
                    unsigned b0, b1, b2, b3;
                    int nrow = base + ((m0 + 1 + (2 * p + (j >> 4)) * 8 + (j & 7)) & 63);
                    ldsm_x4(b0, b1, b2, b3,
                            As + nrow * ASTR + kc + ((j >> 3) & 1) * 8);
                    mma_f16(sacc[2 * p],     a, b0, b1);
                    mma_f16(sacc[2 * p + 1], a, b2, b3);
                }
            }

            float* SsH = Ss + kh * 64 * BSS;
            #pragma unroll
            for (int nt = 0; nt < 4; nt++) {
                int row = m0 + rA;
                int col = nt * 8 + 2 * cA;
                *(float2*)(SsH + row * BSS + col)       = make_float2(sacc[nt][0], sacc[nt][1]);
                *(float2*)(SsH + (row + 8) * BSS + col) = make_float2(sacc[nt][2], sacc[nt][3]);
            }
        }
        __syncthreads();

        #pragma unroll
        for (int it = 0; it < 4; it++) {
            const int v  = it * 16 + w * 2 + g;
            const int dst = Sd[v * 16 + jj];
            const int col = (dst - (v & ~15) - 1) & 63;        // in [0,32)
            float sc = (Ss[v * BSS + col] + Ss[64 * BSS + v * BSS + col]) * 0.0625f;
            float m = sc;
            #pragma unroll
            for (int off = 8; off > 0; off >>= 1) m = fmaxf(m, __shfl_xor_sync(~0u, m, off));
            float e = __expf(sc - m);
            float Zt = e;
            #pragma unroll
            for (int off = 8; off > 0; off >>= 1) Zt += __shfl_xor_sync(~0u, Zt, off);
            const int eIdx = v * 16 + jj;
            g_ewS[((size_t)(b * Lx + l0 + li)) * 1024 + eIdx] =
                skip * Sew[eIdx] + (1.0f - skip) * e / Zt;
        }
        __syncthreads();   // Ss reused by next li
    }
}

// ---------------- K3: transpose ewS (l-major) -> out (e-major) ----------------
__global__ __launch_bounds__(256) void ewT_kernel(float* __restrict__ out)
{
    __shared__ float tile[32][33];
    const int b = blockIdx.z;
    const int l0 = blockIdx.x * 32, e0 = blockIdx.y * 32;
    const int x = threadIdx.x, y = threadIdx.y;
    #pragma unroll
    for (int i = y; i < 32; i += 8)
        tile[i][x] = g_ewS[((size_t)(b * 1024 + l0 + i)) * 1024 + e0 + x];
    __syncthreads();
    float* outEw = out + (size_t)2 * Bx * Ex * Lx;
    #pragma unroll
    for (int i = y; i < 32; i += 8)
        outEw[((size_t)(b * 1024 + e0 + i)) * 1024 + l0 + x] = tile[x][i];
}

extern "C" void kernel_launch(void* const* d_in, const int* in_sizes, int n_in,
                              void* d_out, int out_size)
{
    const float* hs = (const float*)d_in[0];
    const int*   ei = (const int*)  d_in[1];
    const float* ew = (const float*)d_in[2];
    const float* Wq = (const float*)d_in[3];
    const float* bq = (const float*)d_in[4];
    const float* Wk = (const float*)d_in[5];
    const float* bk = (const float*)d_in[6];
    const float* sk = (const float*)d_in[7];
    float* out = (float*)d_out;
    (void)bk;

    pre_a<<<dim3(256, 4), 256>>>(Wq, bq, Wk);
    pre_b<<<256, 256>>>();

    ei_kernel<<<(2 * Bx * Ex * Lx) / (256 * 4), 256>>>(ei, out);

    const int smemF = 128 * ASTR * 2 + 128 * ZSTR * 2 + 4 * 128 * BCH * 2
                    + 256 * 4 + 1024 * 4 + 1024 * 4 + 32;   // 189472 B
    cudaFuncSetAttribute(fused_kernel, cudaFuncAttributeMaxDynamicSharedMemorySize, smemF);
    fused_kernel<<<2048, 256, smemF>>>(hs, ei, ew, sk);

    ewT_kernel<<<dim3(32, 32, Bx), dim3(32, 8)>>>(out);
}